// round 12
// baseline (speedup 1.0000x reference)
#include <cuda_runtime.h>
#include <cuda_bf16.h>
#include <cstdint>

#define B_   32
#define S_   512
#define D_   768
#define EPS_ 1e-8f

#define NCHQ  6                  // 768 / 128 int8-chunks
#define NCTA  128                // persistent CTAs, 2 tiles each
#define TOTCH (2 * NCHQ)         // 12 chunks per CTA

// ---------------- device scratch (chunk-tiled, pre-swizzled int8) ----------------
// layout: [b][kc][row][128 s8], 128B per row, swizzle XOR (row&7)<<4 on byte offset
__device__ __align__(16) int8_t g_q1t[B_ * S_ * D_];
__device__ __align__(16) int8_t g_q2t[B_ * S_ * D_];
__device__ float g_s1[B_ * S_];          // dequant scale per row (>0)
__device__ float g_s2[B_ * S_];
__device__ unsigned g_rowmax[B_ * S_];   // order-preserving mapped fp32
__device__ unsigned g_colmax[B_ * S_];
__device__ int      g_arrive[B_];

// ---------------- helpers ----------------
__device__ __forceinline__ uint32_t smem_u32(const void* p) {
    uint32_t a;
    asm("{ .reg .u64 t; cvta.to.shared.u64 t, %1; cvt.u32.u64 %0, t; }" : "=r"(a) : "l"(p));
    return a;
}
__device__ __forceinline__ unsigned fmap(float x) {
    int i = __float_as_int(x);
    return (unsigned)(i ^ ((i >> 31) | 0x80000000));
}
__device__ __forceinline__ float fumap(unsigned u) {
    int i = (int)(u ^ ((u & 0x80000000u) ? 0x80000000u : 0xFFFFFFFFu));
    return __int_as_float(i);
}

#define MBARRIER_INIT(addr, cnt) \
    asm volatile("mbarrier.init.shared.b64 [%0], %1;" :: "r"(addr), "r"(cnt) : "memory")
#define MBARRIER_EXPECT_TX(addr, bytes) \
    asm volatile("mbarrier.arrive.expect_tx.shared.b64 _, [%0], %1;" :: "r"(addr), "r"(bytes) : "memory")
#define MBARRIER_ARRIVE(addr) \
    asm volatile("mbarrier.arrive.shared.b64 _, [%0];" :: "r"(addr) : "memory")
#define MBARRIER_WAIT_PARITY(mbar_addr, phase_parity) do {                          \
    uint32_t _mbar = (uint32_t)(mbar_addr);                                         \
    uint32_t _par  = (uint32_t)(phase_parity);                                      \
    asm volatile(                                                                   \
        "{\n\t.reg .pred P1;\n\t"                                                   \
        "WAIT_LOOP_%=:\n\t"                                                         \
        "mbarrier.try_wait.parity.acquire.cta.shared::cta.b64 P1, [%0], %1, 0x989680;\n\t" \
        "@P1 bra.uni WAIT_DONE_%=;\n\t"                                             \
        "bra.uni WAIT_LOOP_%=;\n\t"                                                 \
        "WAIT_DONE_%=:\n\t}"                                                        \
        :: "r"(_mbar), "r"(_par) : "memory");                                       \
} while (0)

#define BULK_LOAD(dst, src, size, mbar) \
    asm volatile("cp.async.bulk.shared::cluster.global.mbarrier::complete_tx::bytes " \
                 "[%0], [%1], %2, [%3];" \
                 :: "r"(dst), "l"(src), "r"(size), "r"(mbar) : "memory")

#define LDMATRIX_X4(r0, r1, r2, r3, addr) \
    asm volatile("ldmatrix.sync.aligned.m8n8.x4.shared.b16 {%0,%1,%2,%3}, [%4];" \
                 : "=r"(r0), "=r"(r1), "=r"(r2), "=r"(r3) : "r"(addr))

// ---------------- kernel 1: normalize + int8 quantize (warp per row) ----------
__global__ __launch_bounds__(256) void quantize_kernel(const float* __restrict__ e1,
                                                       const float* __restrict__ e2) {
    const int lane = threadIdx.x & 31;
    const int wrp  = threadIdx.x >> 5;
    const int grow = blockIdx.x * 8 + wrp;      // 0..16383
    const int b    = grow >> 9;
    const int r    = grow & 511;

    if (blockIdx.y == 0 && blockIdx.x < 64) {
        int t = blockIdx.x * 256 + threadIdx.x;   // covers exactly 16384
        g_rowmax[t] = 0u;
        g_colmax[t] = 0u;
        if (t < B_) g_arrive[t] = 0;
    }

    const float* src = (blockIdx.y ? e2 : e1) + (size_t)grow * D_;
    int8_t* dstBase = blockIdx.y ? g_q2t : g_q1t;
    float*  sBase   = blockIdx.y ? g_s2  : g_s1;

    float4 v[6];
    float ss = 0.0f, mm = 0.0f;
    #pragma unroll
    for (int k = 0; k < 6; k++) {
        v[k] = __ldcs((const float4*)(src + lane * 4 + k * 128));
        ss += v[k].x * v[k].x + v[k].y * v[k].y + v[k].z * v[k].z + v[k].w * v[k].w;
        mm = fmaxf(mm, fmaxf(fmaxf(fabsf(v[k].x), fabsf(v[k].y)),
                             fmaxf(fabsf(v[k].z), fabsf(v[k].w))));
    }
    #pragma unroll
    for (int o = 16; o; o >>= 1) {
        ss += __shfl_xor_sync(0xffffffffu, ss, o);
        mm = fmaxf(mm, __shfl_xor_sync(0xffffffffu, mm, o));
    }

    const float norm   = fmaxf(sqrtf(ss), EPS_);
    const float qscale = 127.0f / fmaxf(mm, 1e-30f);
    if (lane == 0) sBase[grow] = mm / (127.0f * norm);

    const int swz = (r & 7) << 4;                 // byte swizzle within 128B row

    #pragma unroll
    for (int k = 0; k < 6; k++) {
        int q0 = max(-127, min(127, __float2int_rn(v[k].x * qscale)));
        int q1 = max(-127, min(127, __float2int_rn(v[k].y * qscale)));
        int q2 = max(-127, min(127, __float2int_rn(v[k].z * qscale)));
        int q3 = max(-127, min(127, __float2int_rn(v[k].w * qscale)));
        unsigned packed = (q0 & 0xff) | ((q1 & 0xff) << 8) |
                          ((q2 & 0xff) << 16) | ((unsigned)(q3 & 0xff) << 24);
        size_t idx = ((size_t)(b * NCHQ + k) * S_ + r) * 128 + (size_t)((lane * 4) ^ swz);
        *(unsigned*)(dstBase + idx) = packed;
    }
}

// ---------------- kernel 2: persistent 2-tile bulk-copy IMMA GEMM ----------------
// CTA tile 128(M)x256(N), 8 warps 2(m)x4(n), warp tile 64x64, mma m16n8k32 s8.
// KC=128 int8 (6 chunks/tile), grid 128, CTA does tiles bid and bid+128.
#define TILE_A_BYTES  16384               // 128 rows x 128B
#define TILE_B_BYTES  32768               // 256 rows x 128B
#define STAGE_BYTES   (TILE_A_BYTES + TILE_B_BYTES)
#define SM_BUF        1024
#define SMEM_TOTAL    (SM_BUF + 3 * STAGE_BYTES)   // 148480

__global__ __launch_bounds__(256, 1) void gemm_max_kernel(const int* __restrict__ mask1,
                                                          const int* __restrict__ mask2,
                                                          float* __restrict__ out) {
    extern __shared__ char smem[];
    const uint32_t sbase = smem_u32(smem);

    const int tid  = threadIdx.x;
    const int lane = tid & 31;
    const int g    = lane >> 2;
    const int tg   = lane & 3;
    const int warp = tid >> 5;
    const int wm   = warp >> 2;       // 0..1
    const int wn   = warp & 3;        // 0..3

    const int bid = blockIdx.x;
    const int off = bid % NCHQ;       // chunk-phase stagger

    int tb[2], ti0[2], tj0[2];
    const int8_t* gA0[2];
    const int8_t* gB0[2];
    #pragma unroll
    for (int ti = 0; ti < 2; ti++) {
        const int t = bid + ti * NCTA;
        tb[ti]  = t >> 3;
        ti0[ti] = ((t >> 1) & 3) * 128;
        tj0[ti] = (t & 1) * 256;
        gA0[ti] = g_q1t + ((size_t)(tb[ti] * NCHQ) * S_ + ti0[ti]) * 128;
        gB0[ti] = g_q2t + ((size_t)(tb[ti] * NCHQ) * S_ + tj0[ti]) * 128;
    }
    const size_t CH_STRIDE = (size_t)S_ * 128;    // bytes per chunk step

    int c[4][8][4];
    #pragma unroll
    for (int mf = 0; mf < 4; mf++)
        #pragma unroll
        for (int nf = 0; nf < 8; nf++)
            #pragma unroll
            for (int e = 0; e < 4; e++) c[mf][nf][e] = 0;

    uint32_t mbF[3], mbE[3], sA[3], sB[3];
    #pragma unroll
    for (int s = 0; s < 3; s++) {
        mbF[s] = sbase + s * 8;
        mbE[s] = sbase + 24 + s * 8;
        sA[s] = sbase + SM_BUF + s * STAGE_BYTES;
        sB[s] = sA[s] + TILE_A_BYTES;
    }

    if (tid == 0) {
        #pragma unroll
        for (int s = 0; s < 3; s++) {
            MBARRIER_INIT(mbF[s], 1);
            MBARRIER_INIT(mbE[s], 8);
        }
    }
    __syncthreads();

    if (tid == 0) {
        #pragma unroll
        for (int p = 0; p < 2; p++) {
            const int cc = (p + off) % NCHQ;      // tile 0 chunks
            MBARRIER_EXPECT_TX(mbF[p], STAGE_BYTES);
            BULK_LOAD(sA[p], gA0[0] + (size_t)cc * CH_STRIDE, TILE_A_BYTES, mbF[p]);
            BULK_LOAD(sB[p], gB0[0] + (size_t)cc * CH_STRIDE, TILE_B_BYTES, mbF[p]);
        }
    }

    // per-lane ldmatrix addressing (swizzled 128B-pitch rows) — byte-identical to bf16 case
    const int ar = wm * 64 + (lane & 15);
    const uint32_t arow = (uint32_t)ar * 128;
    const uint32_t aswz = (uint32_t)(ar & 7) << 4;
    const uint32_t ac0  = (uint32_t)(lane >> 4) * 16;

    const int br = wn * 64 + (lane & 7) + ((lane >> 4) << 3);
    const uint32_t brow = (uint32_t)br * 128;
    const uint32_t bswz = (uint32_t)(br & 7) << 4;
    const uint32_t bc0  = (uint32_t)((lane >> 3) & 1) * 16;

    unsigned af[2][4][4], bfr[2][8][2];

    #pragma unroll 1
    for (int ch = 0; ch < TOTCH; ch++) {
        const int stage = ch % 3;

        if (tid == 0 && ch + 2 < TOTCH) {
            const int c2 = ch + 2;
            const int s2 = c2 % 3;
            MBARRIER_WAIT_PARITY(mbE[s2], ((c2 / 3) & 1) ^ 1);
            const int t2 = c2 / NCHQ;
            const int cc2 = (c2 % NCHQ + off) % NCHQ;
            MBARRIER_EXPECT_TX(mbF[s2], STAGE_BYTES);
            BULK_LOAD(sA[s2], gA0[t2] + (size_t)cc2 * CH_STRIDE, TILE_A_BYTES, mbF[s2]);
            BULK_LOAD(sB[s2], gB0[t2] + (size_t)cc2 * CH_STRIDE, TILE_B_BYTES, mbF[s2]);
        }

        MBARRIER_WAIT_PARITY(mbF[stage], (ch / 3) & 1);

        const uint32_t abase = sA[stage] + arow;
        const uint32_t bbase = sB[stage] + brow;

        #pragma unroll
        for (int mf = 0; mf < 4; mf++)
            LDMATRIX_X4(af[0][mf][0], af[0][mf][1], af[0][mf][2], af[0][mf][3],
                        abase + mf * 2048 + (ac0 ^ aswz));
        #pragma unroll
        for (int p = 0; p < 4; p++) {
            unsigned r0, r1, r2, r3;
            LDMATRIX_X4(r0, r1, r2, r3, bbase + p * 2048 + (bc0 ^ bswz));
            bfr[0][p * 2 + 0][0] = r0; bfr[0][p * 2 + 0][1] = r1;
            bfr[0][p * 2 + 1][0] = r2; bfr[0][p * 2 + 1][1] = r3;
        }

        #pragma unroll
        for (int ks = 0; ks < 4; ks++) {           // 4 x k32 = KC 128
            const int cur = ks & 1, nxt = cur ^ 1;
            if (ks + 1 < 4) {
                const uint32_t kb2 = (uint32_t)(ks + 1) * 32;
                #pragma unroll
                for (int mf = 0; mf < 4; mf++)
                    LDMATRIX_X4(af[nxt][mf][0], af[nxt][mf][1], af[nxt][mf][2], af[nxt][mf][3],
                                abase + mf * 2048 + ((ac0 + kb2) ^ aswz));
                #pragma unroll
                for (int p = 0; p < 4; p++) {
                    unsigned r0, r1, r2, r3;
                    LDMATRIX_X4(r0, r1, r2, r3, bbase + p * 2048 + ((bc0 + kb2) ^ bswz));
                    bfr[nxt][p * 2 + 0][0] = r0; bfr[nxt][p * 2 + 0][1] = r1;
                    bfr[nxt][p * 2 + 1][0] = r2; bfr[nxt][p * 2 + 1][1] = r3;
                }
            }
            #pragma unroll
            for (int mf = 0; mf < 4; mf++)
                #pragma unroll
                for (int nf = 0; nf < 8; nf++)
                    asm volatile(
                        "mma.sync.aligned.m16n8k32.row.col.s32.s8.s8.s32 "
                        "{%0,%1,%2,%3},{%4,%5,%6,%7},{%8,%9},{%0,%1,%2,%3};"
                        : "+r"(c[mf][nf][0]), "+r"(c[mf][nf][1]),
                          "+r"(c[mf][nf][2]), "+r"(c[mf][nf][3])
                        : "r"(af[cur][mf][0]), "r"(af[cur][mf][1]),
                          "r"(af[cur][mf][2]), "r"(af[cur][mf][3]),
                          "r"(bfr[cur][nf][0]), "r"(bfr[cur][nf][1]));
        }

        __syncwarp();
        if (lane == 0) MBARRIER_ARRIVE(mbE[stage]);

        // ================= tile boundary: dequant + epilogue + finalize =================
        if ((ch + 1) % NCHQ == 0) {
            const int ti = ch / NCHQ;
            const int b  = tb[ti];
            const int baseRow = b * S_ + ti0[ti] + wm * 64;
            const int baseCol = b * S_ + tj0[ti] + wn * 64;

            int m1v[4][2], m2v[8][2];
            float s1v[4][2], s2v[8][2];
            #pragma unroll
            for (int mf = 0; mf < 4; mf++) {
                m1v[mf][0] = mask1[baseRow + mf * 16 + g];
                m1v[mf][1] = mask1[baseRow + mf * 16 + g + 8];
                s1v[mf][0] = g_s1[baseRow + mf * 16 + g];
                s1v[mf][1] = g_s1[baseRow + mf * 16 + g + 8];
            }
            #pragma unroll
            for (int nf = 0; nf < 8; nf++) {
                m2v[nf][0] = mask2[baseCol + nf * 8 + 2 * tg];
                m2v[nf][1] = mask2[baseCol + nf * 8 + 2 * tg + 1];
                s2v[nf][0] = g_s2[baseCol + nf * 8 + 2 * tg];
                s2v[nf][1] = g_s2[baseCol + nf * 8 + 2 * tg + 1];
            }

            // row maxes: apply s2 (per-col) before max, s1 (per-row) after reduce
            #pragma unroll
            for (int mf = 0; mf < 4; mf++)
                #pragma unroll
                for (int y = 0; y < 2; y++) {
                    float r = -INFINITY;
                    #pragma unroll
                    for (int nf = 0; nf < 8; nf++) {
                        if (m2v[nf][0]) r = fmaxf(r, (float)c[mf][nf][y * 2 + 0] * s2v[nf][0]);
                        if (m2v[nf][1]) r = fmaxf(r, (float)c[mf][nf][y * 2 + 1] * s2v[nf][1]);
                    }
                    r = fmaxf(r, __shfl_xor_sync(0xffffffffu, r, 1));
                    r = fmaxf(r, __shfl_xor_sync(0xffffffffu, r, 2));
                    if (tg == 0)
                        atomicMax(&g_rowmax[baseRow + mf * 16 + g + 8 * y],
                                  fmap(r * s1v[mf][y]));
                }

            // col maxes: apply s1 (per-row) before max, s2 (per-col) after reduce
            #pragma unroll
            for (int nf = 0; nf < 8; nf++)
                #pragma unroll
                for (int x = 0; x < 2; x++) {
                    float cm = -INFINITY;
                    #pragma unroll
                    for (int mf = 0; mf < 4; mf++) {
                        if (m1v[mf][0]) cm = fmaxf(cm, (float)c[mf][nf][0 * 2 + x] * s1v[mf][0]);
                        if (m1v[mf][1]) cm = fmaxf(cm, (float)c[mf][nf][1 * 2 + x] * s1v[mf][1]);
                    }
                    cm = fmaxf(cm, __shfl_xor_sync(0xffffffffu, cm, 4));
                    cm = fmaxf(cm, __shfl_xor_sync(0xffffffffu, cm, 8));
                    cm = fmaxf(cm, __shfl_xor_sync(0xffffffffu, cm, 16));
                    if (g == 0)
                        atomicMax(&g_colmax[baseCol + nf * 8 + 2 * tg + x],
                                  fmap(cm * s2v[nf][x]));
                }

            // zero accumulators for next tile
            #pragma unroll
            for (int mf = 0; mf < 4; mf++)
                #pragma unroll
                for (int nf = 0; nf < 8; nf++)
                    #pragma unroll
                    for (int e = 0; e < 4; e++) c[mf][nf][e] = 0;

            // finalize: 8th-arriving tile of this batch computes the score
            __shared__ float fsum[8];
            __shared__ int   fcnt[8];
            __shared__ int   s_old;

            __threadfence();
            __syncthreads();
            if (tid == 0) s_old = atomicAdd(&g_arrive[b], 1);
            __syncthreads();
            if (s_old == 7) {
                __threadfence();
                float sum = 0.0f;
                int cnt = 0;
                for (int j = tid; j < S_; j += 256) {
                    int a1 = mask1[b * S_ + j];
                    int a2 = mask2[b * S_ + j];
                    cnt += a1 + a2;
                    if (a1) sum += fumap(__ldcg(&g_rowmax[b * S_ + j]));
                    if (a2) sum += fumap(__ldcg(&g_colmax[b * S_ + j]));
                }
                #pragma unroll
                for (int o = 16; o; o >>= 1) {
                    sum += __shfl_xor_sync(0xffffffffu, sum, o);
                    cnt += __shfl_xor_sync(0xffffffffu, cnt, o);
                }
                if (lane == 0) { fsum[warp] = sum; fcnt[warp] = cnt; }
                __syncthreads();
                if (tid == 0) {
                    float ts = 0.f; int tc = 0;
                    #pragma unroll
                    for (int i = 0; i < 8; i++) { ts += fsum[i]; tc += fcnt[i]; }
                    out[b] = ts / fmaxf((float)tc, 1.0f);
                    g_arrive[b] = 0;   // reset for graph replay
                }
            }
        }
    }
}

// ---------------- launch ----------------
extern "C" void kernel_launch(void* const* d_in, const int* in_sizes, int n_in,
                              void* d_out, int out_size) {
    const float* emb1 = (const float*)d_in[0];
    const float* emb2 = (const float*)d_in[1];
    const int*   mask1 = (const int*)d_in[2];
    const int*   mask2 = (const int*)d_in[3];
    float* out = (float*)d_out;

    cudaFuncSetAttribute(gemm_max_kernel,
                         cudaFuncAttributeMaxDynamicSharedMemorySize, SMEM_TOTAL);

    quantize_kernel<<<dim3(2048, 2), 256>>>(emb1, emb2);
    gemm_max_kernel<<<NCTA, 256, SMEM_TOTAL>>>(mask1, mask2, out);
}

// round 13
// speedup vs baseline: 3.2531x; 3.2531x over previous
#include <cuda_runtime.h>
#include <cuda_bf16.h>
#include <cstdint>

#define B_   32
#define S_   512
#define D_   768
#define EPS_ 1e-8f

#define KC    64
#define NCH   (D_ / KC)          // 12

// ---------------- device scratch ----------------
// compacted, chunk-tiled, pre-swizzled bf16: [b][kc][slot][64], 128B rows
__device__ __align__(16) __nv_bfloat16 g_n1t[B_ * S_ * D_];
__device__ __align__(16) __nv_bfloat16 g_n2t[B_ * S_ * D_];
__device__ int g_pos1[B_ * S_], g_pos2[B_ * S_];    // exclusive prefix of mask
__device__ int g_idx1[B_ * S_], g_idx2[B_ * S_];    // slot -> original row
__device__ int g_cnt1[B_], g_cnt2[B_];
__device__ unsigned g_rowmax[B_ * S_];   // order-preserving mapped fp32
__device__ unsigned g_colmax[B_ * S_];
__device__ int      g_arrive[B_];

// ---------------- helpers ----------------
__device__ __forceinline__ uint32_t smem_u32(const void* p) {
    uint32_t a;
    asm("{ .reg .u64 t; cvta.to.shared.u64 t, %1; cvt.u32.u64 %0, t; }" : "=r"(a) : "l"(p));
    return a;
}
__device__ __forceinline__ unsigned fmap(float x) {
    int i = __float_as_int(x);
    return (unsigned)(i ^ ((i >> 31) | 0x80000000));
}
__device__ __forceinline__ float fumap(unsigned u) {
    int i = (int)(u ^ ((u & 0x80000000u) ? 0x80000000u : 0xFFFFFFFFu));
    return __int_as_float(i);
}

#define MBARRIER_INIT(addr, cnt) \
    asm volatile("mbarrier.init.shared.b64 [%0], %1;" :: "r"(addr), "r"(cnt) : "memory")
#define MBARRIER_EXPECT_TX(addr, bytes) \
    asm volatile("mbarrier.arrive.expect_tx.shared.b64 _, [%0], %1;" :: "r"(addr), "r"(bytes) : "memory")
#define MBARRIER_ARRIVE(addr) \
    asm volatile("mbarrier.arrive.shared.b64 _, [%0];" :: "r"(addr) : "memory")
#define MBARRIER_WAIT_PARITY(mbar_addr, phase_parity) do {                          \
    uint32_t _mbar = (uint32_t)(mbar_addr);                                         \
    uint32_t _par  = (uint32_t)(phase_parity);                                      \
    asm volatile(                                                                   \
        "{\n\t.reg .pred P1;\n\t"                                                   \
        "WAIT_LOOP_%=:\n\t"                                                         \
        "mbarrier.try_wait.parity.acquire.cta.shared::cta.b64 P1, [%0], %1, 0x989680;\n\t" \
        "@P1 bra.uni WAIT_DONE_%=;\n\t"                                             \
        "bra.uni WAIT_LOOP_%=;\n\t"                                                 \
        "WAIT_DONE_%=:\n\t}"                                                        \
        :: "r"(_mbar), "r"(_par) : "memory");                                       \
} while (0)

#define BULK_LOAD(dst, src, size, mbar) \
    asm volatile("cp.async.bulk.shared::cluster.global.mbarrier::complete_tx::bytes " \
                 "[%0], [%1], %2, [%3];" \
                 :: "r"(dst), "l"(src), "r"(size), "r"(mbar) : "memory")

#define LDMATRIX_X4(r0, r1, r2, r3, addr) \
    asm volatile("ldmatrix.sync.aligned.m8n8.x4.shared.b16 {%0,%1,%2,%3}, [%4];" \
                 : "=r"(r0), "=r"(r1), "=r"(r2), "=r"(r3) : "r"(addr))

// ---------------- kernel 0: per-batch mask prefix scan ----------------
__global__ __launch_bounds__(512) void prefix_kernel(const int* __restrict__ m1,
                                                     const int* __restrict__ m2) {
    const int b = blockIdx.x;
    const int* m = blockIdx.y ? m2 : m1;
    int* pos = blockIdx.y ? g_pos2 : g_pos1;
    int* cnt = blockIdx.y ? g_cnt2 : g_cnt1;
    const int t = threadIdx.x, lane = t & 31, w = t >> 5;

    const int v = (m[b * S_ + t] != 0);
    unsigned bal = __ballot_sync(0xffffffffu, v);
    int pre = __popc(bal & ((1u << lane) - 1u));

    __shared__ int wsum[16], woff[16];
    if (lane == 31) wsum[w] = pre + v;
    __syncthreads();
    if (t == 0) {
        int run = 0;
        #pragma unroll
        for (int i = 0; i < 16; i++) { woff[i] = run; run += wsum[i]; }
        cnt[b] = run;
    }
    __syncthreads();
    pos[b * S_ + t] = woff[w] + pre;
}

// ---------------- kernel 1: normalize valid rows -> compacted tiled layout ------
__global__ __launch_bounds__(256) void normalize_kernel(const float* __restrict__ e1,
                                                        const float* __restrict__ e2,
                                                        const int* __restrict__ mask1,
                                                        const int* __restrict__ mask2) {
    const int lane = threadIdx.x & 31;
    const int wrp  = threadIdx.x >> 5;
    const int grow = blockIdx.x * 8 + wrp;      // 0..16383
    const int b    = grow >> 9;
    const int r    = grow & 511;

    if (blockIdx.y == 0 && blockIdx.x < 64) {
        int t = blockIdx.x * 256 + threadIdx.x;   // covers exactly 16384
        g_rowmax[t] = 0u;
        g_colmax[t] = 0u;
        if (t < B_) g_arrive[t] = 0;
    }

    const int valid = (blockIdx.y ? mask2 : mask1)[grow];
    if (!valid) return;

    const int slot = (blockIdx.y ? g_pos2 : g_pos1)[grow];
    if (lane == 0) (blockIdx.y ? g_idx2 : g_idx1)[b * S_ + slot] = r;

    const float* src = (blockIdx.y ? e2 : e1) + (size_t)grow * D_;
    __nv_bfloat16* dstBase = blockIdx.y ? g_n2t : g_n1t;

    float4 v[6];
    float ss = 0.0f;
    #pragma unroll
    for (int k = 0; k < 6; k++) {
        v[k] = __ldcs((const float4*)(src + lane * 4 + k * 128));
        ss += v[k].x * v[k].x + v[k].y * v[k].y + v[k].z * v[k].z + v[k].w * v[k].w;
    }
    #pragma unroll
    for (int o = 16; o; o >>= 1) ss += __shfl_xor_sync(0xffffffffu, ss, o);

    const float s = 1.0f / fmaxf(sqrtf(ss), EPS_);
    const int swz = (slot & 7) << 3;              // bf16-unit swizzle within 64-col row

    #pragma unroll
    for (int k = 0; k < 6; k++) {
        int cg = lane * 4 + k * 128;
        int kc = cg >> 6;
        int c  = cg & 63;
        size_t idx = ((size_t)(b * NCH + kc) * S_ + slot) * 64 + (size_t)(c ^ swz);
        *(__nv_bfloat162*)(dstBase + idx)     = __floats2bfloat162_rn(v[k].x * s, v[k].y * s);
        *(__nv_bfloat162*)(dstBase + idx + 2) = __floats2bfloat162_rn(v[k].z * s, v[k].w * s);
    }
}

// ---------------- kernel 2: compacted bulk-copy HMMA GEMM ----------------
// CTA tile 128x128, 4 warps 2(m)x2(n), warp tile 64x64, mma m16n8k16 bf16.
// grid (4,4,32); CTAs beyond the compacted counts exit to finalize-arrive.
#define TILE_BYTES  16384                 // 128 rows x 128B (A and B)
#define STAGE_BYTES (2 * TILE_BYTES)
#define SM_BUF      1024
#define SMEM_TOTAL  (SM_BUF + 3 * STAGE_BYTES)   // 99328

__global__ __launch_bounds__(128, 2) void gemm_max_kernel(const int* __restrict__ mask1,
                                                          const int* __restrict__ mask2,
                                                          float* __restrict__ out) {
    extern __shared__ char smem[];
    const uint32_t sbase = smem_u32(smem);

    const int tid  = threadIdx.x;
    const int lane = tid & 31;
    const int g    = lane >> 2;
    const int tg   = lane & 3;
    const int warp = tid >> 5;        // 0..3
    const int wm   = warp >> 1;       // 0..1
    const int wn   = warp & 1;        // 0..1

    const int b  = blockIdx.z;
    const int i0 = blockIdx.y * 128;
    const int j0 = blockIdx.x * 128;
    const int bid = blockIdx.x + 4 * blockIdx.y + 16 * b;
    const int off = bid % NCH;

    const int c1 = g_cnt1[b];
    const int c2 = g_cnt2[b];
    const bool active = (i0 < c1) && (j0 < c2);

    if (active) {
        float c[4][8][4];
        #pragma unroll
        for (int mf = 0; mf < 4; mf++)
            #pragma unroll
            for (int nf = 0; nf < 8; nf++)
                #pragma unroll
                for (int e = 0; e < 4; e++) c[mf][nf][e] = 0.0f;

        uint32_t mbF[3], mbE[3], sA[3], sB[3];
        #pragma unroll
        for (int s = 0; s < 3; s++) {
            mbF[s] = sbase + s * 8;
            mbE[s] = sbase + 24 + s * 8;
            sA[s] = sbase + SM_BUF + s * STAGE_BYTES;
            sB[s] = sA[s] + TILE_BYTES;
        }

        if (tid == 0) {
            #pragma unroll
            for (int s = 0; s < 3; s++) {
                MBARRIER_INIT(mbF[s], 1);
                MBARRIER_INIT(mbE[s], 4);         // one arrive per warp
            }
        }
        __syncthreads();

        const __nv_bfloat16* gA0 = g_n1t + ((size_t)(b * NCH) * S_ + i0) * 64;
        const __nv_bfloat16* gB0 = g_n2t + ((size_t)(b * NCH) * S_ + j0) * 64;
        const size_t CH_STRIDE = (size_t)S_ * 64;

        if (tid == 0) {
            #pragma unroll
            for (int p = 0; p < 2; p++) {
                const int cc = (p + off) % NCH;
                MBARRIER_EXPECT_TX(mbF[p], STAGE_BYTES);
                BULK_LOAD(sA[p], gA0 + (size_t)cc * CH_STRIDE, TILE_BYTES, mbF[p]);
                BULK_LOAD(sB[p], gB0 + (size_t)cc * CH_STRIDE, TILE_BYTES, mbF[p]);
            }
        }

        const int ar = wm * 64 + (lane & 15);
        const uint32_t arow = (uint32_t)ar * 128;
        const uint32_t aswz = (uint32_t)(ar & 7) << 4;
        const uint32_t ac0  = (uint32_t)(lane >> 4) * 16;

        const int br = wn * 64 + (lane & 7) + ((lane >> 4) << 3);
        const uint32_t brow = (uint32_t)br * 128;
        const uint32_t bswz = (uint32_t)(br & 7) << 4;
        const uint32_t bc0  = (uint32_t)((lane >> 3) & 1) * 16;

        unsigned af[2][4][4], bfr[2][8][2];

        #pragma unroll 1
        for (int ch = 0; ch < NCH; ch++) {
            const int stage = ch % 3;

            if (tid == 0 && ch + 2 < NCH) {
                const int cn = ch + 2;
                const int s2 = cn % 3;
                MBARRIER_WAIT_PARITY(mbE[s2], ((cn / 3) & 1) ^ 1);
                const int cc2 = (cn + off) % NCH;
                MBARRIER_EXPECT_TX(mbF[s2], STAGE_BYTES);
                BULK_LOAD(sA[s2], gA0 + (size_t)cc2 * CH_STRIDE, TILE_BYTES, mbF[s2]);
                BULK_LOAD(sB[s2], gB0 + (size_t)cc2 * CH_STRIDE, TILE_BYTES, mbF[s2]);
            }

            MBARRIER_WAIT_PARITY(mbF[stage], (ch / 3) & 1);

            const uint32_t abase = sA[stage] + arow;
            const uint32_t bbase = sB[stage] + brow;

            #pragma unroll
            for (int mf = 0; mf < 4; mf++)
                LDMATRIX_X4(af[0][mf][0], af[0][mf][1], af[0][mf][2], af[0][mf][3],
                            abase + mf * 2048 + (ac0 ^ aswz));
            #pragma unroll
            for (int p = 0; p < 4; p++) {
                unsigned r0, r1, r2, r3;
                LDMATRIX_X4(r0, r1, r2, r3, bbase + p * 2048 + (bc0 ^ bswz));
                bfr[0][p * 2 + 0][0] = r0; bfr[0][p * 2 + 0][1] = r1;
                bfr[0][p * 2 + 1][0] = r2; bfr[0][p * 2 + 1][1] = r3;
            }

            #pragma unroll
            for (int ks = 0; ks < KC / 16; ks++) {
                const int cur = ks & 1, nxt = cur ^ 1;
                if (ks + 1 < KC / 16) {
                    const uint32_t kb2 = (uint32_t)(ks + 1) * 32;
                    #pragma unroll
                    for (int mf = 0; mf < 4; mf++)
                        LDMATRIX_X4(af[nxt][mf][0], af[nxt][mf][1], af[nxt][mf][2], af[nxt][mf][3],
                                    abase + mf * 2048 + ((ac0 + kb2) ^ aswz));
                    #pragma unroll
                    for (int p = 0; p < 4; p++) {
                        unsigned r0, r1, r2, r3;
                        LDMATRIX_X4(r0, r1, r2, r3, bbase + p * 2048 + ((bc0 + kb2) ^ bswz));
                        bfr[nxt][p * 2 + 0][0] = r0; bfr[nxt][p * 2 + 0][1] = r1;
                        bfr[nxt][p * 2 + 1][0] = r2; bfr[nxt][p * 2 + 1][1] = r3;
                    }
                }
                #pragma unroll
                for (int mf = 0; mf < 4; mf++)
                    #pragma unroll
                    for (int nf = 0; nf < 8; nf++)
                        asm volatile(
                            "mma.sync.aligned.m16n8k16.row.col.f32.bf16.bf16.f32 "
                            "{%0,%1,%2,%3},{%4,%5,%6,%7},{%8,%9},{%0,%1,%2,%3};"
                            : "+f"(c[mf][nf][0]), "+f"(c[mf][nf][1]),
                              "+f"(c[mf][nf][2]), "+f"(c[mf][nf][3])
                            : "r"(af[cur][mf][0]), "r"(af[cur][mf][1]),
                              "r"(af[cur][mf][2]), "r"(af[cur][mf][3]),
                              "r"(bfr[cur][nf][0]), "r"(bfr[cur][nf][1]));
            }

            __syncwarp();
            if (lane == 0) MBARRIER_ARRIVE(mbE[stage]);
        }

        // -------- epilogue: validity = slot < count; atomics via index map --------
        const int rowSlotBase = i0 + wm * 64;
        const int colSlotBase = j0 + wn * 64;

        int rOK[4][2], rIdx[4][2];
        #pragma unroll
        for (int mf = 0; mf < 4; mf++)
            #pragma unroll
            for (int y = 0; y < 2; y++) {
                int slot = rowSlotBase + mf * 16 + g + 8 * y;
                rOK[mf][y] = (slot < c1);
                rIdx[mf][y] = rOK[mf][y] ? g_idx1[b * S_ + slot] : 0;
            }
        int cOK[8][2], cIdx[8][2];
        #pragma unroll
        for (int nf = 0; nf < 8; nf++)
            #pragma unroll
            for (int x = 0; x < 2; x++) {
                int slot = colSlotBase + nf * 8 + 2 * tg + x;
                cOK[nf][x] = (slot < c2);
                cIdx[nf][x] = cOK[nf][x] ? g_idx2[b * S_ + slot] : 0;
            }

        #pragma unroll
        for (int mf = 0; mf < 4; mf++)
            #pragma unroll
            for (int y = 0; y < 2; y++) {
                float r = -INFINITY;
                #pragma unroll
                for (int nf = 0; nf < 8; nf++) {
                    if (cOK[nf][0]) r = fmaxf(r, c[mf][nf][y * 2 + 0]);
                    if (cOK[nf][1]) r = fmaxf(r, c[mf][nf][y * 2 + 1]);
                }
                r = fmaxf(r, __shfl_xor_sync(0xffffffffu, r, 1));
                r = fmaxf(r, __shfl_xor_sync(0xffffffffu, r, 2));
                if (tg == 0 && rOK[mf][y])
                    atomicMax(&g_rowmax[b * S_ + rIdx[mf][y]], fmap(r));
            }

        #pragma unroll
        for (int nf = 0; nf < 8; nf++)
            #pragma unroll
            for (int x = 0; x < 2; x++) {
                float cm = -INFINITY;
                #pragma unroll
                for (int mf = 0; mf < 4; mf++) {
                    if (rOK[mf][0]) cm = fmaxf(cm, c[mf][nf][0 * 2 + x]);
                    if (rOK[mf][1]) cm = fmaxf(cm, c[mf][nf][1 * 2 + x]);
                }
                cm = fmaxf(cm, __shfl_xor_sync(0xffffffffu, cm, 4));
                cm = fmaxf(cm, __shfl_xor_sync(0xffffffffu, cm, 8));
                cm = fmaxf(cm, __shfl_xor_sync(0xffffffffu, cm, 16));
                if (g == 0 && cOK[nf][x])
                    atomicMax(&g_colmax[b * S_ + cIdx[nf][x]], fmap(cm));
            }
    }

    // -------- finalize: 16th-arriving CTA of this batch computes score --------
    __shared__ float fsum[4];
    __shared__ int   fcnt[4];
    __shared__ int   s_old;

    __threadfence();
    __syncthreads();
    if (tid == 0) s_old = atomicAdd(&g_arrive[b], 1);
    __syncthreads();
    if (s_old == 15) {
        __threadfence();
        float sum = 0.0f;
        int cnt = 0;
        for (int j = tid; j < S_; j += 128) {
            int a1 = mask1[b * S_ + j];
            int a2 = mask2[b * S_ + j];
            cnt += a1 + a2;
            if (a1) sum += fumap(__ldcg(&g_rowmax[b * S_ + j]));
            if (a2) sum += fumap(__ldcg(&g_colmax[b * S_ + j]));
        }
        #pragma unroll
        for (int o = 16; o; o >>= 1) {
            sum += __shfl_xor_sync(0xffffffffu, sum, o);
            cnt += __shfl_xor_sync(0xffffffffu, cnt, o);
        }
        if (lane == 0) { fsum[warp] = sum; fcnt[warp] = cnt; }
        __syncthreads();
        if (tid == 0) {
            float ts = 0.f; int tc = 0;
            #pragma unroll
            for (int i = 0; i < 4; i++) { ts += fsum[i]; tc += fcnt[i]; }
            out[b] = ts / fmaxf((float)tc, 1.0f);
            g_arrive[b] = 0;   // reset for graph replay
        }
    }
}

// ---------------- launch ----------------
extern "C" void kernel_launch(void* const* d_in, const int* in_sizes, int n_in,
                              void* d_out, int out_size) {
    const float* emb1 = (const float*)d_in[0];
    const float* emb2 = (const float*)d_in[1];
    const int*   mask1 = (const int*)d_in[2];
    const int*   mask2 = (const int*)d_in[3];
    float* out = (float*)d_out;

    cudaFuncSetAttribute(gemm_max_kernel,
                         cudaFuncAttributeMaxDynamicSharedMemorySize, SMEM_TOTAL);

    prefix_kernel<<<dim3(B_, 2), 512>>>(mask1, mask2);
    normalize_kernel<<<dim3(2048, 2), 256>>>(emb1, emb2, mask1, mask2);
    gemm_max_kernel<<<dim3(4, 4, B_), 128, SMEM_TOTAL>>>(mask1, mask2, out);
}